// round 7
// baseline (speedup 1.0000x reference)
#include <cuda_runtime.h>
#include <cuda_fp16.h>

#define H    128   // hidden dim
#define HPH  64    // h per half
#define TPB  256   // threads per block (two 128-thread halves)
#define UPB  128   // point-units per block
#define PPT  4     // points per unit (2 point-pairs)
#define NPR  2     // point-pairs per thread
#define CH   8     // h-chunk size between fp32 flushes

__device__ __forceinline__ unsigned h2u(__half2 v) {
    return *reinterpret_cast<unsigned*>(&v);
}
__device__ __forceinline__ __half2 u2h(unsigned v) {
    return *reinterpret_cast<__half2*>(&v);
}

__global__ __launch_bounds__(TPB)
void cubeflow_fused_kernel(const float* __restrict__ input,
                           const float* __restrict__ latent,
                           const float* __restrict__ W1,
                           const float* __restrict__ b1,
                           const float* __restrict__ W2,
                           const float* __restrict__ b2,
                           float* __restrict__ out,
                           int P, int BP)
{
    // fp16 weights, each half2 = (w,w) duplicated.
    __shared__ uint4 sW[H];        // {w0w0, w1w1, w2w2, bTbT}  bT = w3*theta+b1
    __shared__ uint4 sV[H / 2];    // {v0(h),v1(h), v0(h+1),v1(h+1)} 2 h per entry
    __shared__ float4 redA[UPB];   // cross-half partial probs (pts 0,1)
    __shared__ float4 redB[UPB];   // cross-half partial probs (pts 2,3)

    const int tid    = threadIdx.x;
    const int wg_tid = tid & (UPB - 1);
    const int half   = tid >> 7;                  // 0: h[0,64)  1: h[64,128)

    // theta uniform per block (block spans 512 contiguous points in one batch)
    const int   bidx  = (blockIdx.x * (UPB * PPT)) / P;
    const float theta = latent[bidx] * 10.0f;

    if (tid < H) {
        const float4 r = reinterpret_cast<const float4*>(W1)[tid];
        const float bT = fmaf(r.w, theta, b1[tid]);
        sW[tid] = make_uint4(h2u(__float2half2_rn(r.x)),
                             h2u(__float2half2_rn(r.y)),
                             h2u(__float2half2_rn(r.z)),
                             h2u(__float2half2_rn(bT)));
    }
    if (tid < H / 2) {
        const int h0 = 2 * tid, h1 = h0 + 1;
        sV[tid] = make_uint4(h2u(__float2half2_rn(W2[h0])),
                             h2u(__float2half2_rn(W2[H + h0])),
                             h2u(__float2half2_rn(W2[h1])),
                             h2u(__float2half2_rn(W2[H + h1])));
    }

    const int unit = blockIdx.x * UPB + wg_tid;   // one unit = 4 points
    const int p0   = unit * PPT;

    // 4 points * 3 coords = 3 coalesced float4 loads (both halves load)
    const float4* in4 = reinterpret_cast<const float4*>(input) + (size_t)unit * 3;
    const float4 q0 = in4[0], q1 = in4[1], q2 = in4[2];
    const float x0[PPT] = { q0.x, q0.w, q1.z, q2.y };
    const float x1[PPT] = { q0.y, q1.x, q1.w, q2.z };
    const float x2[PPT] = { q0.z, q1.y, q2.x, q2.w };

    // All fp32 scalar-x work first (exact outputs: con + eval).
    if (half == 0) {
        float4* conp = reinterpret_cast<float4*>(out + BP) + p0;
        #pragma unroll
        for (int k = 0; k < PPT; ++k)
            conp[k] = make_float4(x0[k], x1[k], x2[k], theta);
    } else {
        float sn, cs;
        sincosf(theta, &sn, &cs);
        float ev[PPT];
        #pragma unroll
        for (int k = 0; k < PPT; ++k) {
            const float d0 = x0[k] - theta, d1 = x1[k], d2 = x2[k];
            const float f1 = 1.4f * (d0 * d0) + 1.4f * (d1 * d1)
                           + 0.2f * (d2 * d2) - 0.5f;
            const float a2  = d2 + 0.4f;
            const float c20 = d0 * cs + d1 * sn;
            const float c21 = d1 * cs - d0 * sn;
            const float f2v = 3.8f * c20 * c20 + 0.6f * c21 * c21
                            + 3.8f * a2 * a2 - 0.5f;
            const float a3  = d2 - 0.6f;
            const float c30 = d0 * cs - d1 * sn;
            const float c31 = d0 * sn + d1 * cs;
            const float f3v = 0.35f * c30 * c30 + 2.8f * c31 * c31
                            + 2.8f * a3 * a3 - 0.5f;
            ev[k] = fminf(f1, fminf(f2v, f3v));
        }
        *reinterpret_cast<float4*>(out + p0) =
            make_float4(ev[0], ev[1], ev[2], ev[3]);
    }

    // ---- fp16 MLP: two adjacent points per half2 lane ----
    __half2 X0[NPR], X1[NPR], X2[NPR];
    float2  A0[NPR], A1[NPR];   // fp32 output accumulators
    #pragma unroll
    for (int j = 0; j < NPR; ++j) {
        X0[j] = __floats2half2_rn(x0[2 * j], x0[2 * j + 1]);
        X1[j] = __floats2half2_rn(x1[2 * j], x1[2 * j + 1]);
        X2[j] = __floats2half2_rn(x2[2 * j], x2[2 * j + 1]);
        A0[j] = make_float2(0.f, 0.f);
        A1[j] = make_float2(0.f, 0.f);
    }

    __syncthreads();

    const uint4* pw = sW + half * HPH;
    const uint4* pv = sV + half * (HPH / 2);
    const __half2 zero = __float2half2_rn(0.f);

    #pragma unroll 1
    for (int c = 0; c < HPH / CH; ++c) {            // 8 chunks of 8 h
        // ---- batch ALL chunk weight loads first (one scoreboard wait) ----
        uint4 W[CH];
        uint4 V[CH / 2];
        #pragma unroll
        for (int i = 0; i < CH; ++i)     W[i] = pw[c * CH + i];
        #pragma unroll
        for (int i = 0; i < CH / 2; ++i) V[i] = pv[c * (CH / 2) + i];

        __half2 P0[NPR], P1[NPR];                   // fp16 partials (8-h window)
        #pragma unroll
        for (int j = 0; j < NPR; ++j) { P0[j] = zero; P1[j] = zero; }

        #pragma unroll
        for (int i = 0; i < CH; ++i) {
            const __half2 w0 = u2h(W[i].x), w1 = u2h(W[i].y);
            const __half2 w2 = u2h(W[i].z), bT = u2h(W[i].w);
            const __half2 v0 = u2h((i & 1) ? V[i >> 1].z : V[i >> 1].x);
            const __half2 v1 = u2h((i & 1) ? V[i >> 1].w : V[i >> 1].y);
            #pragma unroll
            for (int j = 0; j < NPR; ++j) {
                __half2 t = __hfma2(w0, X0[j],
                            __hfma2(w1, X1[j],
                            __hfma2(w2, X2[j], bT)));
                t = __hmax2(t, zero);               // relu
                P0[j] = __hfma2(v0, t, P0[j]);
                P1[j] = __hfma2(v1, t, P1[j]);
            }
        }

        #pragma unroll
        for (int j = 0; j < NPR; ++j) {             // flush to fp32
            const float2 f0 = __half22float2(P0[j]);
            const float2 f1 = __half22float2(P1[j]);
            A0[j].x += f0.x;  A0[j].y += f0.y;
            A1[j].x += f1.x;  A1[j].y += f1.y;
        }
    }

    // per-point partial probs
    float pr0[PPT], pr1[PPT];
    #pragma unroll
    for (int j = 0; j < NPR; ++j) {
        pr0[2 * j]     = A0[j].x;  pr0[2 * j + 1] = A0[j].y;
        pr1[2 * j]     = A1[j].x;  pr1[2 * j + 1] = A1[j].y;
    }

    if (half == 1) {
        redA[wg_tid] = make_float4(pr0[0], pr1[0], pr0[1], pr1[1]);
        redB[wg_tid] = make_float4(pr0[2], pr1[2], pr0[3], pr1[3]);
    }
    __syncthreads();

    if (half == 0) {
        const float b20 = __ldg(b2), b21 = __ldg(b2 + 1);
        const float4 rA = redA[wg_tid];
        const float4 rB = redB[wg_tid];
        float4* prp = reinterpret_cast<float4*>(out + (size_t)5 * BP
                                                + (size_t)p0 * 2);
        prp[0] = make_float4(pr0[0] + rA.x + b20, pr1[0] + rA.y + b21,
                             pr0[1] + rA.z + b20, pr1[1] + rA.w + b21);
        prp[1] = make_float4(pr0[2] + rB.x + b20, pr1[2] + rB.y + b21,
                             pr0[3] + rB.z + b20, pr1[3] + rB.w + b21);
    }
}

extern "C" void kernel_launch(void* const* d_in, const int* in_sizes, int n_in,
                              void* d_out, int out_size)
{
    const float* input  = (const float*)d_in[0];
    const float* latent = (const float*)d_in[1];
    const float* W1     = (const float*)d_in[2];
    const float* b1     = (const float*)d_in[3];
    const float* W2     = (const float*)d_in[4];
    const float* b2     = (const float*)d_in[5];
    float*       out    = (float*)d_out;

    const int BP = in_sizes[0] / 3;        // total points (B*P)
    const int B  = in_sizes[1];            // latent element count == batch
    const int P  = BP / B;
    const int blocks = BP / (UPB * PPT);   // 1024

    cubeflow_fused_kernel<<<blocks, TPB>>>(input, latent, W1, b1, W2, b2,
                                           out, P, BP);
}